// round 6
// baseline (speedup 1.0000x reference)
#include <cuda_runtime.h>

namespace {
constexpr int HH     = 256;
constexpr int WW     = 256;
constexpr int NC     = 64;
constexpr int DYN    = 32;
constexpr int TILE_W = 32;
constexpr int TILE_H = 4;
constexpr int SH     = 8;            // TILE_H + 4 halo rows
constexpr int SW     = 40;           // 36 used + pad; 160B row stride
constexpr int NTHR   = 32;           // ONE warp per CTA
constexpr int PLANE  = HH * WW;
constexpr int ROW_CHUNKS = 18;       // 36 floats / 2 per 8B chunk
constexpr int CHUNKS = SH * ROW_CHUNKS;   // 144
}

__device__ __forceinline__ ulonglong2 ld128s(const float* p) {
    return *reinterpret_cast<const ulonglong2*>(p);
}
__device__ __forceinline__ void unpk(unsigned long long v, float& a, float& b) {
    asm("mov.b64 {%0, %1}, %2;" : "=f"(a), "=f"(b) : "l"(v));
}
__device__ __forceinline__ unsigned long long pk(float a, float b) {
    unsigned long long v;
    asm("mov.b64 %0, {%1, %2};" : "=l"(v) : "f"(a), "f"(b));
    return v;
}
__device__ __forceinline__ unsigned long long ffma2(unsigned long long a,
                                                    unsigned long long b,
                                                    unsigned long long c) {
    unsigned long long d;
    asm("fma.rn.f32x2 %0, %1, %2, %3;" : "=l"(d) : "l"(a), "l"(b), "l"(c));
    return d;
}
__device__ __forceinline__ unsigned smem_u32(const void* p) {
    unsigned r;
    asm("{ .reg .u64 t; cvta.to.shared.u64 t, %1; cvt.u32.u64 %0, t; }"
        : "=r"(r) : "l"(p));
    return r;
}

// Prefetch one channel tile via 8-byte cp.async chunks (shifted layout:
// tile col t <-> global col w0-2+t). OOB chunks skipped; buffers pre-zeroed.
__device__ __forceinline__ void prefetch_tile(unsigned smem_base,
                                              const float* __restrict__ plane,
                                              int h0, int w0, int tid) {
#pragma unroll
    for (int i = 0; i < 5; i++) {
        int idx = tid + i * NTHR;
        if (idx < CHUNKS) {
            int r  = idx / ROW_CHUNKS;
            int c  = idx - r * ROW_CHUNKS;
            int gh = h0 + r - 2;
            int gw = w0 - 2 + 2 * c;
            if ((unsigned)gh < (unsigned)HH && gw >= 0 && gw + 2 <= WW) {
                unsigned dst = smem_base + (unsigned)(r * SW + 2 * c) * 4u;
                const float* src = plane + gh * WW + gw;
                asm volatile("cp.async.ca.shared.global [%0], [%1], 8;\n"
                             :: "r"(dst), "l"(src));
            }
        }
    }
    asm volatile("cp.async.commit_group;\n");
}

// One row of score accumulation. Two aligned LDS.128 cover cols 4tx..4tx+7.
// Pairs: P0=(4tx,+1) P1=(+2,+3) P2=(+4,+5) P3=(+6,+7). Pixels at cols +2..+5.
#define SCORE_BODY(P0, P1, P2, P3, r)                                         \
    {                                                                         \
        float p0x, p0y, p1x, p1y, p2x, p2y, p3x, p3y;                         \
        unpk(P0, p0x, p0y); unpk(P1, p1x, p1y);                               \
        unpk(P2, p2x, p2y); unpk(P3, p3x, p3y);                               \
        (void)p0x; (void)p3y;                                                 \
        sA[(r)*3+0] = ffma2(P0, cA, sA[(r)*3+0]);                             \
        sA[(r)*3+1] = ffma2(P1, cA, sA[(r)*3+1]);                             \
        sA[(r)*3+2] = ffma2(P2, cA, sA[(r)*3+2]);                             \
        sB[(r)*3+0] = ffma2(P1, cB, sB[(r)*3+0]);                             \
        sB[(r)*3+1] = ffma2(P2, cB, sB[(r)*3+1]);                             \
        sB[(r)*3+2] = ffma2(P3, cB, sB[(r)*3+2]);                             \
        oA0[(r)*2+0] = fmaf(p0y, cA0, oA0[(r)*2+0]);                          \
        oA1[(r)*2+0] = fmaf(p1x, cA1, oA1[(r)*2+0]);                          \
        oA0[(r)*2+1] = fmaf(p1y, cA0, oA0[(r)*2+1]);                          \
        oA1[(r)*2+1] = fmaf(p2x, cA1, oA1[(r)*2+1]);                          \
        oB0[(r)*2+0] = fmaf(p1y, cB0, oB0[(r)*2+0]);                          \
        oB1[(r)*2+0] = fmaf(p2x, cB1, oB1[(r)*2+0]);                          \
        oB0[(r)*2+1] = fmaf(p2y, cB0, oB0[(r)*2+1]);                          \
        oB1[(r)*2+1] = fmaf(p3x, cB1, oB1[(r)*2+1]);                          \
    }

#define SCORE_ROW(r)                                                          \
    {                                                                         \
        const float* rowp = tbase + (ty + (r)) * SW + 4 * tx;                 \
        ulonglong2 g0 = ld128s(rowp);                                         \
        ulonglong2 g1 = ld128s(rowp + 4);                                     \
        SCORE_BODY(g0.x, g0.y, g1.x, g1.y, r)                                 \
    }

extern "C" __global__ void __launch_bounds__(NTHR, 16)
local_attn_kernel(const float* __restrict__ x, const float* __restrict__ kern,
                  float* __restrict__ out) {
    const int tid = threadIdx.x;
    const int tx  = tid & 7;
    const int ty  = tid >> 3;           // 0..3
    const int b   = blockIdx.z;
    const int h0  = blockIdx.y * TILE_H;
    const int w0  = blockIdx.x * TILE_W;
    const int h   = h0 + ty;
    const int w   = w0 + 4 * tx;

    __shared__ __align__(16) float tiles[3][SH * SW];
    __shared__ float kw[32];
    if (tid < 25) kw[tid] = kern[tid] * 0.2f;   // kernel[k] / KSIZE

    // zero-fill all buffers once (border locations stay zero forever)
    {
        float4 z = make_float4(0.f, 0.f, 0.f, 0.f);
        float4* tz = reinterpret_cast<float4*>(&tiles[0][0]);
        const int n4 = 3 * SH * SW / 4;   // 240
#pragma unroll
        for (int i = 0; i < 8; i++) {
            int idx = tid + i * NTHR;
            if (idx < n4) tz[idx] = z;
        }
    }
    __syncwarp();

    const float* base = x + (size_t)b * NC * PLANE;
    unsigned sbuf[3] = { smem_u32(&tiles[0][0]), smem_u32(&tiles[1][0]),
                         smem_u32(&tiles[2][0]) };

    prefetch_tile(sbuf[0], base + (size_t)(DYN + 0) * PLANE, h0, w0, tid);
    prefetch_tile(sbuf[1], base + (size_t)(DYN + 1) * PLANE, h0, w0, tid);

    // accumulators: even-j taps packed f32x2, odd-j taps scalar
    unsigned long long sA[15], sB[15];
    float oA0[10], oA1[10], oB0[10], oB1[10];
#pragma unroll
    for (int i = 0; i < 15; i++) { sA[i] = 0ull; sB[i] = 0ull; }
#pragma unroll
    for (int i = 0; i < 10; i++) { oA0[i] = 0.f; oA1[i] = 0.f; oB0[i] = 0.f; oB1[i] = 0.f; }

    float inv0 = 0.f, inv1 = 0.f, inv2 = 0.f, inv3 = 0.f;
    float* outp = out + (size_t)b * DYN * PLANE + h * WW + w;

    for (int i = 0; i < 2 * 32; i++) {
        asm volatile("cp.async.wait_group 1;\n" ::: "memory");
        __syncwarp();
        if (i + 2 < 64) {
            int ch = (i + 2 < 32) ? (DYN + i + 2) : (i + 2 - 32);
            prefetch_tile(sbuf[(i + 2) % 3], base + (size_t)ch * PLANE, h0, w0, tid);
        } else {
            asm volatile("cp.async.commit_group;\n");   // keep group counts uniform
        }

        const float* tbase = &tiles[i % 3][0];

        if (i < 32) {
            // ---- Phase 1: scores (static channels). Center row (r=2) first;
            // center pairs cA/cB come from that row's own two loads. ----
            unsigned long long cA, cB;
            float cA0, cA1, cB0, cB1;
            {
                const float* rowp = tbase + (ty + 2) * SW + 4 * tx;
                ulonglong2 g0 = ld128s(rowp);
                ulonglong2 g1 = ld128s(rowp + 4);
                cA = g0.y; cB = g1.x;
                unpk(cA, cA0, cA1); unpk(cB, cB0, cB1);
                SCORE_BODY(g0.x, g0.y, g1.x, g1.y, 2)
            }
            SCORE_ROW(0)
            SCORE_ROW(1)
            SCORE_ROW(3)
            SCORE_ROW(4)
        } else {
            if (i == 32) {
                // ---- Softmax over 25 taps (per pixel), once ----
                float m0 = -3.0e38f, m1 = m0, m2 = m0, m3 = m0;
#pragma unroll
                for (int q = 0; q < 5; q++) {
#pragma unroll
                    for (int jj = 0; jj < 3; jj++) {
                        float kk = kw[q * 5 + 2 * jj];
                        float s0, s1, s2, s3;
                        unpk(sA[q*3+jj], s0, s1); unpk(sB[q*3+jj], s2, s3);
                        s0 *= kk; s1 *= kk; s2 *= kk; s3 *= kk;
                        sA[q*3+jj] = pk(s0, s1); sB[q*3+jj] = pk(s2, s3);
                        m0 = fmaxf(m0, s0); m1 = fmaxf(m1, s1);
                        m2 = fmaxf(m2, s2); m3 = fmaxf(m3, s3);
                    }
#pragma unroll
                    for (int jj = 0; jj < 2; jj++) {
                        float kk = kw[q * 5 + 2 * jj + 1];
                        oA0[q*2+jj] *= kk; oA1[q*2+jj] *= kk;
                        oB0[q*2+jj] *= kk; oB1[q*2+jj] *= kk;
                        m0 = fmaxf(m0, oA0[q*2+jj]); m1 = fmaxf(m1, oA1[q*2+jj]);
                        m2 = fmaxf(m2, oB0[q*2+jj]); m3 = fmaxf(m3, oB1[q*2+jj]);
                    }
                }
                float t0 = 0.f, t1 = 0.f, t2 = 0.f, t3 = 0.f;
#pragma unroll
                for (int q = 0; q < 15; q++) {
                    float s0, s1, s2, s3;
                    unpk(sA[q], s0, s1); unpk(sB[q], s2, s3);
                    s0 = __expf(s0 - m0); s1 = __expf(s1 - m1);
                    s2 = __expf(s2 - m2); s3 = __expf(s3 - m3);
                    t0 += s0; t1 += s1; t2 += s2; t3 += s3;
                    sA[q] = pk(s0, s1); sB[q] = pk(s2, s3);
                }
#pragma unroll
                for (int q = 0; q < 10; q++) {
                    float e0 = __expf(oA0[q] - m0), e1 = __expf(oA1[q] - m1);
                    float e2 = __expf(oB0[q] - m2), e3 = __expf(oB1[q] - m3);
                    oA0[q] = e0; oA1[q] = e1; oB0[q] = e2; oB1[q] = e3;
                    t0 += e0; t1 += e1; t2 += e2; t3 += e3;
                }
                inv0 = __fdividef(1.f, t0); inv1 = __fdividef(1.f, t1);
                inv2 = __fdividef(1.f, t2); inv3 = __fdividef(1.f, t3);
            }

            // ---- Phase 2: weighted sum (dynamic channels) ----
            unsigned long long accA = 0ull, accB = 0ull;
            float a0 = 0.f, a1 = 0.f, a2 = 0.f, a3 = 0.f;
#pragma unroll
            for (int r = 0; r < 5; r++) {
                const float* rowp = tbase + (ty + r) * SW + 4 * tx;
                ulonglong2 g0 = ld128s(rowp);
                ulonglong2 g1 = ld128s(rowp + 4);
                unsigned long long P0 = g0.x, P1 = g0.y, P2 = g1.x, P3 = g1.y;
                float p0x, p0y, p1x, p1y, p2x, p2y, p3x, p3y;
                unpk(P0, p0x, p0y); unpk(P1, p1x, p1y);
                unpk(P2, p2x, p2y); unpk(P3, p3x, p3y);
                (void)p0x; (void)p3y;

                accA = ffma2(P0, sA[r*3+0], accA);
                accA = ffma2(P1, sA[r*3+1], accA);
                accA = ffma2(P2, sA[r*3+2], accA);
                accB = ffma2(P1, sB[r*3+0], accB);
                accB = ffma2(P2, sB[r*3+1], accB);
                accB = ffma2(P3, sB[r*3+2], accB);

                a0 = fmaf(p0y, oA0[r*2+0], a0);
                a1 = fmaf(p1x, oA1[r*2+0], a1);
                a0 = fmaf(p1y, oA0[r*2+1], a0);
                a1 = fmaf(p2x, oA1[r*2+1], a1);
                a2 = fmaf(p1y, oB0[r*2+0], a2);
                a3 = fmaf(p2x, oB1[r*2+0], a3);
                a2 = fmaf(p2y, oB0[r*2+1], a2);
                a3 = fmaf(p3x, oB1[r*2+1], a3);
            }
            float A0, A1, Bv0, Bv1;
            unpk(accA, A0, A1); unpk(accB, Bv0, Bv1);
            float4 res;
            res.x = (A0 + a0) * inv0;
            res.y = (A1 + a1) * inv1;
            res.z = (Bv0 + a2) * inv2;
            res.w = (Bv1 + a3) * inv3;
            *reinterpret_cast<float4*>(outp + (size_t)(i - 32) * PLANE) = res;
        }
    }
}

extern "C" void kernel_launch(void* const* d_in, const int* in_sizes, int n_in,
                              void* d_out, int out_size) {
    const float* x = (const float*)d_in[0];
    const float* k = (const float*)d_in[1];
    float* o       = (float*)d_out;
    dim3 block(NTHR, 1, 1);
    dim3 grid(WW / TILE_W, HH / TILE_H, 4);   // 8 x 64 x 4 = 2048 blocks
    local_attn_kernel<<<grid, block>>>(x, k, o);
}

// round 7
// speedup vs baseline: 1.0771x; 1.0771x over previous
#include <cuda_runtime.h>

namespace {
constexpr int HH     = 256;
constexpr int WW     = 256;
constexpr int NC     = 64;
constexpr int DYN    = 32;
constexpr int TILE_W = 32;
constexpr int TILE_H = 8;
constexpr int SH     = 12;           // TILE_H + 4 halo rows
constexpr int SW     = 40;           // 36 used + 4 pad; 160B row stride
constexpr int NTHR   = 64;
constexpr int PLANE  = HH * WW;
constexpr int ROW_CHUNKS = 18;       // 36 floats / 2 per 8B chunk
constexpr int CHUNKS = SH * ROW_CHUNKS;   // 216
}

__device__ __forceinline__ ulonglong2 ld128s(const float* p) {
    return *reinterpret_cast<const ulonglong2*>(p);
}
__device__ __forceinline__ void unpk(unsigned long long v, float& a, float& b) {
    asm("mov.b64 {%0, %1}, %2;" : "=f"(a), "=f"(b) : "l"(v));
}
__device__ __forceinline__ unsigned long long pk(float a, float b) {
    unsigned long long v;
    asm("mov.b64 %0, {%1, %2};" : "=l"(v) : "f"(a), "f"(b));
    return v;
}
__device__ __forceinline__ unsigned long long ffma2(unsigned long long a,
                                                    unsigned long long b,
                                                    unsigned long long c) {
    unsigned long long d;
    asm("fma.rn.f32x2 %0, %1, %2, %3;" : "=l"(d) : "l"(a), "l"(b), "l"(c));
    return d;
}
__device__ __forceinline__ unsigned smem_u32(const void* p) {
    unsigned r;
    asm("{ .reg .u64 t; cvta.to.shared.u64 t, %1; cvt.u32.u64 %0, t; }"
        : "=r"(r) : "l"(p));
    return r;
}

// Prefetch one channel tile via 8-byte cp.async chunks (shifted layout:
// tile col t <-> global col w0-2+t). OOB chunks skipped; buffers pre-zeroed.
__device__ __forceinline__ void prefetch_tile(unsigned smem_base,
                                              const float* __restrict__ plane,
                                              int h0, int w0, int tid) {
#pragma unroll
    for (int i = 0; i < 4; i++) {
        int idx = tid + i * NTHR;
        if (idx < CHUNKS) {
            int r  = idx / ROW_CHUNKS;
            int c  = idx - r * ROW_CHUNKS;
            int gh = h0 + r - 2;
            int gw = w0 - 2 + 2 * c;
            if ((unsigned)gh < (unsigned)HH && gw >= 0 && gw + 2 <= WW) {
                unsigned dst = smem_base + (unsigned)(r * SW + 2 * c) * 4u;
                const float* src = plane + gh * WW + gw;
                asm volatile("cp.async.ca.shared.global [%0], [%1], 8;\n"
                             :: "r"(dst), "l"(src));
            }
        }
    }
    asm volatile("cp.async.commit_group;\n");
}

// One row of score accumulation. Two aligned LDS.128 cover cols 4tx..4tx+7
// (shifted layout => taps of pixels 4tx..4tx+3 exactly).
// Pairs: P0=(4tx,+1) P1=(+2,+3) P2=(+4,+5) P3=(+6,+7).
#define SCORE_BODY(P0, P1, P2, P3, r)                                         \
    {                                                                         \
        float p0x, p0y, p1x, p1y, p2x, p2y, p3x, p3y;                         \
        unpk(P0, p0x, p0y); unpk(P1, p1x, p1y);                               \
        unpk(P2, p2x, p2y); unpk(P3, p3x, p3y);                               \
        (void)p0x; (void)p3y;                                                 \
        sA[(r)*3+0] = ffma2(P0, cA, sA[(r)*3+0]);                             \
        sA[(r)*3+1] = ffma2(P1, cA, sA[(r)*3+1]);                             \
        sA[(r)*3+2] = ffma2(P2, cA, sA[(r)*3+2]);                             \
        sB[(r)*3+0] = ffma2(P1, cB, sB[(r)*3+0]);                             \
        sB[(r)*3+1] = ffma2(P2, cB, sB[(r)*3+1]);                             \
        sB[(r)*3+2] = ffma2(P3, cB, sB[(r)*3+2]);                             \
        oA0[(r)*2+0] = fmaf(p0y, cA0, oA0[(r)*2+0]);                          \
        oA1[(r)*2+0] = fmaf(p1x, cA1, oA1[(r)*2+0]);                          \
        oA0[(r)*2+1] = fmaf(p1y, cA0, oA0[(r)*2+1]);                          \
        oA1[(r)*2+1] = fmaf(p2x, cA1, oA1[(r)*2+1]);                          \
        oB0[(r)*2+0] = fmaf(p1y, cB0, oB0[(r)*2+0]);                          \
        oB1[(r)*2+0] = fmaf(p2x, cB1, oB1[(r)*2+0]);                          \
        oB0[(r)*2+1] = fmaf(p2y, cB0, oB0[(r)*2+1]);                          \
        oB1[(r)*2+1] = fmaf(p3x, cB1, oB1[(r)*2+1]);                          \
    }

#define SCORE_ROW(r)                                                          \
    {                                                                         \
        const float* rowp = tbase + (ty + (r)) * SW + 4 * tx;                 \
        ulonglong2 g0 = ld128s(rowp);                                         \
        ulonglong2 g1 = ld128s(rowp + 4);                                     \
        SCORE_BODY(g0.x, g0.y, g1.x, g1.y, r)                                 \
    }

extern "C" __global__ void __launch_bounds__(NTHR, 8)
local_attn_kernel(const float* __restrict__ x, const float* __restrict__ kern,
                  float* __restrict__ out) {
    const int tid = threadIdx.x;
    const int tx  = tid & 7;
    const int ty  = tid >> 3;           // 0..7
    const int b   = blockIdx.z;
    const int h0  = blockIdx.y * TILE_H;
    const int w0  = blockIdx.x * TILE_W;
    const int h   = h0 + ty;
    const int w   = w0 + 4 * tx;

    __shared__ __align__(16) float tiles[3][SH * SW];
    __shared__ float kw[32];
    if (tid < 25) kw[tid] = kern[tid] * 0.2f;   // kernel[k] / KSIZE

    // zero-fill all buffers once (border locations stay zero forever)
    {
        float4 z = make_float4(0.f, 0.f, 0.f, 0.f);
        float4* tz = reinterpret_cast<float4*>(&tiles[0][0]);
        const int n4 = 3 * SH * SW / 4;   // 360
#pragma unroll
        for (int i = 0; i < 6; i++) {
            int idx = tid + i * NTHR;
            if (idx < n4) tz[idx] = z;
        }
    }
    __syncthreads();

    const float* base = x + (size_t)b * NC * PLANE;
    unsigned sbuf[3] = { smem_u32(&tiles[0][0]), smem_u32(&tiles[1][0]),
                         smem_u32(&tiles[2][0]) };

    prefetch_tile(sbuf[0], base + (size_t)(DYN + 0) * PLANE, h0, w0, tid);
    prefetch_tile(sbuf[1], base + (size_t)(DYN + 1) * PLANE, h0, w0, tid);

    // accumulators: even-j taps packed f32x2, odd-j taps scalar
    unsigned long long sA[15], sB[15];
    float oA0[10], oA1[10], oB0[10], oB1[10];
#pragma unroll
    for (int i = 0; i < 15; i++) { sA[i] = 0ull; sB[i] = 0ull; }
#pragma unroll
    for (int i = 0; i < 10; i++) { oA0[i] = 0.f; oA1[i] = 0.f; oB0[i] = 0.f; oB1[i] = 0.f; }

    float inv0 = 0.f, inv1 = 0.f, inv2 = 0.f, inv3 = 0.f;
    float* outp = out + (size_t)b * DYN * PLANE + h * WW + w;

    for (int i = 0; i < 2 * 32; i++) {
        asm volatile("cp.async.wait_group 1;\n" ::: "memory");
        __syncthreads();
        if (i + 2 < 64) {
            int ch = (i + 2 < 32) ? (DYN + i + 2) : (i + 2 - 32);
            prefetch_tile(sbuf[(i + 2) % 3], base + (size_t)ch * PLANE, h0, w0, tid);
        } else {
            asm volatile("cp.async.commit_group;\n");   // keep group counts uniform
        }

        const float* tbase = &tiles[i % 3][0];

        if (i < 32) {
            // ---- Phase 1: scores (static channels). Center row (r=2) first;
            // center pairs cA/cB come from that row's own two loads. ----
            unsigned long long cA, cB;
            float cA0, cA1, cB0, cB1;
            {
                const float* rowp = tbase + (ty + 2) * SW + 4 * tx;
                ulonglong2 g0 = ld128s(rowp);
                ulonglong2 g1 = ld128s(rowp + 4);
                cA = g0.y; cB = g1.x;
                unpk(cA, cA0, cA1); unpk(cB, cB0, cB1);
                SCORE_BODY(g0.x, g0.y, g1.x, g1.y, 2)
            }
            SCORE_ROW(0)
            SCORE_ROW(1)
            SCORE_ROW(3)
            SCORE_ROW(4)
        } else {
            if (i == 32) {
                // ---- Softmax over 25 taps (per pixel), once ----
                float m0 = -3.0e38f, m1 = m0, m2 = m0, m3 = m0;
#pragma unroll
                for (int q = 0; q < 5; q++) {
#pragma unroll
                    for (int jj = 0; jj < 3; jj++) {
                        float kk = kw[q * 5 + 2 * jj];
                        float s0, s1, s2, s3;
                        unpk(sA[q*3+jj], s0, s1); unpk(sB[q*3+jj], s2, s3);
                        s0 *= kk; s1 *= kk; s2 *= kk; s3 *= kk;
                        sA[q*3+jj] = pk(s0, s1); sB[q*3+jj] = pk(s2, s3);
                        m0 = fmaxf(m0, s0); m1 = fmaxf(m1, s1);
                        m2 = fmaxf(m2, s2); m3 = fmaxf(m3, s3);
                    }
#pragma unroll
                    for (int jj = 0; jj < 2; jj++) {
                        float kk = kw[q * 5 + 2 * jj + 1];
                        oA0[q*2+jj] *= kk; oA1[q*2+jj] *= kk;
                        oB0[q*2+jj] *= kk; oB1[q*2+jj] *= kk;
                        m0 = fmaxf(m0, oA0[q*2+jj]); m1 = fmaxf(m1, oA1[q*2+jj]);
                        m2 = fmaxf(m2, oB0[q*2+jj]); m3 = fmaxf(m3, oB1[q*2+jj]);
                    }
                }
                float t0 = 0.f, t1 = 0.f, t2 = 0.f, t3 = 0.f;
#pragma unroll
                for (int q = 0; q < 15; q++) {
                    float s0, s1, s2, s3;
                    unpk(sA[q], s0, s1); unpk(sB[q], s2, s3);
                    s0 = __expf(s0 - m0); s1 = __expf(s1 - m1);
                    s2 = __expf(s2 - m2); s3 = __expf(s3 - m3);
                    t0 += s0; t1 += s1; t2 += s2; t3 += s3;
                    sA[q] = pk(s0, s1); sB[q] = pk(s2, s3);
                }
#pragma unroll
                for (int q = 0; q < 10; q++) {
                    float e0 = __expf(oA0[q] - m0), e1 = __expf(oA1[q] - m1);
                    float e2 = __expf(oB0[q] - m2), e3 = __expf(oB1[q] - m3);
                    oA0[q] = e0; oA1[q] = e1; oB0[q] = e2; oB1[q] = e3;
                    t0 += e0; t1 += e1; t2 += e2; t3 += e3;
                }
                inv0 = __fdividef(1.f, t0); inv1 = __fdividef(1.f, t1);
                inv2 = __fdividef(1.f, t2); inv3 = __fdividef(1.f, t3);
            }

            // ---- Phase 2: weighted sum (dynamic channels) ----
            unsigned long long accA = 0ull, accB = 0ull;
            float a0 = 0.f, a1 = 0.f, a2 = 0.f, a3 = 0.f;
#pragma unroll
            for (int r = 0; r < 5; r++) {
                const float* rowp = tbase + (ty + r) * SW + 4 * tx;
                ulonglong2 g0 = ld128s(rowp);
                ulonglong2 g1 = ld128s(rowp + 4);
                unsigned long long P0 = g0.x, P1 = g0.y, P2 = g1.x, P3 = g1.y;
                float p0x, p0y, p1x, p1y, p2x, p2y, p3x, p3y;
                unpk(P0, p0x, p0y); unpk(P1, p1x, p1y);
                unpk(P2, p2x, p2y); unpk(P3, p3x, p3y);
                (void)p0x; (void)p3y;

                accA = ffma2(P0, sA[r*3+0], accA);
                accA = ffma2(P1, sA[r*3+1], accA);
                accA = ffma2(P2, sA[r*3+2], accA);
                accB = ffma2(P1, sB[r*3+0], accB);
                accB = ffma2(P2, sB[r*3+1], accB);
                accB = ffma2(P3, sB[r*3+2], accB);

                a0 = fmaf(p0y, oA0[r*2+0], a0);
                a1 = fmaf(p1x, oA1[r*2+0], a1);
                a0 = fmaf(p1y, oA0[r*2+1], a0);
                a1 = fmaf(p2x, oA1[r*2+1], a1);
                a2 = fmaf(p1y, oB0[r*2+0], a2);
                a3 = fmaf(p2x, oB1[r*2+0], a3);
                a2 = fmaf(p2y, oB0[r*2+1], a2);
                a3 = fmaf(p3x, oB1[r*2+1], a3);
            }
            float A0, A1, Bv0, Bv1;
            unpk(accA, A0, A1); unpk(accB, Bv0, Bv1);
            float4 res;
            res.x = (A0 + a0) * inv0;
            res.y = (A1 + a1) * inv1;
            res.z = (Bv0 + a2) * inv2;
            res.w = (Bv1 + a3) * inv3;
            *reinterpret_cast<float4*>(outp + (size_t)(i - 32) * PLANE) = res;
        }
    }
}

extern "C" void kernel_launch(void* const* d_in, const int* in_sizes, int n_in,
                              void* d_out, int out_size) {
    const float* x = (const float*)d_in[0];
    const float* k = (const float*)d_in[1];
    float* o       = (float*)d_out;
    dim3 block(NTHR, 1, 1);
    dim3 grid(WW / TILE_W, HH / TILE_H, 4);   // 8 x 32 x 4 = 1024 blocks
    local_attn_kernel<<<grid, block>>>(x, k, o);
}

// round 10
// speedup vs baseline: 1.4437x; 1.3403x over previous
#include <cuda_runtime.h>

namespace {
constexpr int HH     = 256;
constexpr int WW     = 256;
constexpr int NC     = 64;
constexpr int DYN    = 32;
constexpr int TILE_W = 32;
constexpr int TILE_H = 8;
constexpr int SH     = 12;           // TILE_H + 4 halo rows
constexpr int SW     = 40;           // halo ±4 cols, 160B rows (16B aligned)
constexpr int NTHR   = 64;
constexpr int PLANE  = HH * WW;
constexpr int ROW_CHUNKS = 10;       // 40 floats = 10 x 16B
constexpr int CHUNKS = SH * ROW_CHUNKS;   // 120
constexpr int TELEMS = SH * SW;      // 480 floats per channel tile
constexpr int TBYTES = TELEMS * 4;   // 1920 bytes
}

__device__ __forceinline__ ulonglong2 ld128s(const float* p) {
    return *reinterpret_cast<const ulonglong2*>(p);
}
__device__ __forceinline__ void unpk(unsigned long long v, float& a, float& b) {
    asm("mov.b64 {%0, %1}, %2;" : "=f"(a), "=f"(b) : "l"(v));
}
__device__ __forceinline__ unsigned long long pk(float a, float b) {
    unsigned long long v;
    asm("mov.b64 %0, {%1, %2};" : "=l"(v) : "f"(a), "f"(b));
    return v;
}
__device__ __forceinline__ unsigned long long ffma2(unsigned long long a,
                                                    unsigned long long b,
                                                    unsigned long long c) {
    unsigned long long d;
    asm("fma.rn.f32x2 %0, %1, %2, %3;" : "=l"(d) : "l"(a), "l"(b), "l"(c));
    return d;
}
__device__ __forceinline__ unsigned smem_u32(const void* p) {
    unsigned r;
    asm("{ .reg .u64 t; cvta.to.shared.u64 t, %1; cvt.u32.u64 %0, t; }"
        : "=r"(r) : "l"(p));
    return r;
}
__device__ __forceinline__ void cp16(unsigned dst, const float* src) {
    asm volatile("cp.async.cg.shared.global [%0], [%1], 16;\n"
                 :: "r"(dst), "l"(src));
}

// One row of score accumulation (layout: tile col t <-> global w0-4+t).
// Taps of the 4 pixels live at tile cols 4tx+2..4tx+9 => quads g0,g1,g2.
#define SCORE_BODY(P0, P1, P2, P3, r)                                         \
    {                                                                         \
        float p0x, p0y, p1x, p1y, p2x, p2y, p3x, p3y;                         \
        unpk(P0, p0x, p0y); unpk(P1, p1x, p1y);                               \
        unpk(P2, p2x, p2y); unpk(P3, p3x, p3y);                               \
        (void)p0x; (void)p3y;                                                 \
        sA[(r)*3+0] = ffma2(P0, cA, sA[(r)*3+0]);                             \
        sA[(r)*3+1] = ffma2(P1, cA, sA[(r)*3+1]);                             \
        sA[(r)*3+2] = ffma2(P2, cA, sA[(r)*3+2]);                             \
        sB[(r)*3+0] = ffma2(P1, cB, sB[(r)*3+0]);                             \
        sB[(r)*3+1] = ffma2(P2, cB, sB[(r)*3+1]);                             \
        sB[(r)*3+2] = ffma2(P3, cB, sB[(r)*3+2]);                             \
        oA0[(r)*2+0] = fmaf(p0y, cA0, oA0[(r)*2+0]);                          \
        oA1[(r)*2+0] = fmaf(p1x, cA1, oA1[(r)*2+0]);                          \
        oA0[(r)*2+1] = fmaf(p1y, cA0, oA0[(r)*2+1]);                          \
        oA1[(r)*2+1] = fmaf(p2x, cA1, oA1[(r)*2+1]);                          \
        oB0[(r)*2+0] = fmaf(p1y, cB0, oB0[(r)*2+0]);                          \
        oB1[(r)*2+0] = fmaf(p2x, cB1, oB1[(r)*2+0]);                          \
        oB0[(r)*2+1] = fmaf(p2y, cB0, oB0[(r)*2+1]);                          \
        oB1[(r)*2+1] = fmaf(p3x, cB1, oB1[(r)*2+1]);                          \
    }

#define SCORE_ROW(r)                                                          \
    {                                                                         \
        const float* rowp = tbase + (ty + (r)) * SW + 4 * tx;                 \
        ulonglong2 g0 = ld128s(rowp);                                         \
        ulonglong2 g1 = ld128s(rowp + 4);                                     \
        ulonglong2 g2 = ld128s(rowp + 8);                                     \
        SCORE_BODY(g0.y, g1.x, g1.y, g2.x, r)                                 \
    }

// Full phase-1 pass over one channel tile (center row first; center pair is
// the middle quad of row ty+2, no extra load).
#define PHASE1(TB)                                                            \
    {                                                                         \
        const float* tbase = (TB);                                            \
        unsigned long long cA, cB;                                            \
        float cA0, cA1, cB0, cB1;                                             \
        {                                                                     \
            const float* rowp = tbase + (ty + 2) * SW + 4 * tx;               \
            ulonglong2 g0 = ld128s(rowp);                                     \
            ulonglong2 g1 = ld128s(rowp + 4);                                 \
            ulonglong2 g2 = ld128s(rowp + 8);                                 \
            cA = g1.x; cB = g1.y;                                             \
            unpk(cA, cA0, cA1); unpk(cB, cB0, cB1);                           \
            SCORE_BODY(g0.y, g1.x, g1.y, g2.x, 2)                             \
        }                                                                     \
        SCORE_ROW(0)                                                          \
        SCORE_ROW(1)                                                          \
        SCORE_ROW(3)                                                          \
        SCORE_ROW(4)                                                          \
    }

// Full phase-2 pass over one channel tile, storing output channel CH.
#define PHASE2(TB, CH)                                                        \
    {                                                                         \
        const float* tbase = (TB);                                            \
        unsigned long long accA = 0ull, accB = 0ull;                          \
        float a0 = 0.f, a1 = 0.f, a2 = 0.f, a3 = 0.f;                         \
        _Pragma("unroll")                                                     \
        for (int r = 0; r < 5; r++) {                                         \
            const float* rowp = tbase + (ty + r) * SW + 4 * tx;               \
            ulonglong2 g0 = ld128s(rowp);                                     \
            ulonglong2 g1 = ld128s(rowp + 4);                                 \
            ulonglong2 g2 = ld128s(rowp + 8);                                 \
            unsigned long long P0 = g0.y, P1 = g1.x, P2 = g1.y, P3 = g2.x;    \
            float p0x, p0y, p1x, p1y, p2x, p2y, p3x, p3y;                     \
            unpk(P0, p0x, p0y); unpk(P1, p1x, p1y);                           \
            unpk(P2, p2x, p2y); unpk(P3, p3x, p3y);                           \
            (void)p0x; (void)p3y;                                             \
            accA = ffma2(P0, sA[r*3+0], accA);                                \
            accA = ffma2(P1, sA[r*3+1], accA);                                \
            accA = ffma2(P2, sA[r*3+2], accA);                                \
            accB = ffma2(P1, sB[r*3+0], accB);                                \
            accB = ffma2(P2, sB[r*3+1], accB);                                \
            accB = ffma2(P3, sB[r*3+2], accB);                                \
            a0 = fmaf(p0y, oA0[r*2+0], a0);                                   \
            a1 = fmaf(p1x, oA1[r*2+0], a1);                                   \
            a0 = fmaf(p1y, oA0[r*2+1], a0);                                   \
            a1 = fmaf(p2x, oA1[r*2+1], a1);                                   \
            a2 = fmaf(p1y, oB0[r*2+0], a2);                                   \
            a3 = fmaf(p2x, oB1[r*2+0], a3);                                   \
            a2 = fmaf(p2y, oB0[r*2+1], a2);                                   \
            a3 = fmaf(p3x, oB1[r*2+1], a3);                                   \
        }                                                                     \
        float A0, A1, Bv0, Bv1;                                               \
        unpk(accA, A0, A1); unpk(accB, Bv0, Bv1);                             \
        float4 res;                                                           \
        res.x = (A0 + a0) * inv0;                                             \
        res.y = (A1 + a1) * inv1;                                             \
        res.z = (Bv0 + a2) * inv2;                                            \
        res.w = (Bv1 + a3) * inv3;                                            \
        *reinterpret_cast<float4*>(outp + (size_t)(CH) * PLANE) = res;        \
    }

extern "C" __global__ void __launch_bounds__(NTHR, 7)
local_attn_kernel(const float* __restrict__ x, const float* __restrict__ kern,
                  float* __restrict__ out) {
    const int tid = threadIdx.x;
    const int tx  = tid & 7;
    const int ty  = tid >> 3;           // 0..7
    const int b   = blockIdx.z;
    const int h0  = blockIdx.y * TILE_H;
    const int w0  = blockIdx.x * TILE_W;
    const int h   = h0 + ty;
    const int w   = w0 + 4 * tx;

    __shared__ __align__(16) float tiles[3][2 * TELEMS];   // slot = 2 channels
    __shared__ float kw[32];
    if (tid < 25) kw[tid] = kern[tid] * 0.2f;   // kernel[k] / KSIZE

    // zero-fill all buffers once (border chunks stay zero forever)
    {
        float4 z = make_float4(0.f, 0.f, 0.f, 0.f);
        float4* tz = reinterpret_cast<float4*>(&tiles[0][0]);
        const int n4 = 3 * 2 * TELEMS / 4;   // 720
#pragma unroll
        for (int i = 0; i < 12; i++) {
            int idx = tid + i * NTHR;
            if (idx < n4) tz[idx] = z;
        }
    }
    __syncthreads();

    // ---- Precompute prefetch chunk descriptors (channel-invariant) ----
    bool vA, vB;
    unsigned soA, soB;
    int goA, goB;
    {
        int idx = tid;                       // chunk 0: always < 120
        int r = idx / ROW_CHUNKS, c = idx - r * ROW_CHUNKS;
        int gh = h0 + r - 2, gw = w0 - 4 + 4 * c;
        vA  = ((unsigned)gh < (unsigned)HH) && (gw >= 0) && (gw + 4 <= WW);
        soA = (unsigned)(r * SW + 4 * c) * 4u;
        goA = gh * WW + gw;

        idx = tid + NTHR;                    // chunk 1: valid only if < 120
        r = idx / ROW_CHUNKS; c = idx - r * ROW_CHUNKS;
        gh = h0 + r - 2; gw = w0 - 4 + 4 * c;
        vB  = (idx < CHUNKS) && ((unsigned)gh < (unsigned)HH) &&
              (gw >= 0) && (gw + 4 <= WW);
        soB = (unsigned)(r * SW + 4 * c) * 4u;
        goB = gh * WW + gw;
    }

    const float* base = x + (size_t)b * NC * PLANE;
    unsigned sbuf[3] = { smem_u32(&tiles[0][0]), smem_u32(&tiles[1][0]),
                         smem_u32(&tiles[2][0]) };

    // prefetch a 2-channel pair into slot sb; planeA = first channel plane
    auto pf = [&](unsigned sb, const float* planeA) {
        if (vA) { cp16(sb + soA, planeA + goA);
                  cp16(sb + TBYTES + soA, planeA + PLANE + goA); }
        if (vB) { cp16(sb + soB, planeA + goB);
                  cp16(sb + TBYTES + soB, planeA + PLANE + goB); }
        asm volatile("cp.async.commit_group;\n");
    };

    pf(sbuf[0], base + (size_t)(DYN + 0) * PLANE);   // pair 0: ch 32,33
    pf(sbuf[1], base + (size_t)(DYN + 2) * PLANE);   // pair 1: ch 34,35

    // accumulators: even-j taps packed f32x2, odd-j taps scalar
    unsigned long long sA[15], sB[15];
    float oA0[10], oA1[10], oB0[10], oB1[10];
#pragma unroll
    for (int i = 0; i < 15; i++) { sA[i] = 0ull; sB[i] = 0ull; }
#pragma unroll
    for (int i = 0; i < 10; i++) { oA0[i] = 0.f; oA1[i] = 0.f; oB0[i] = 0.f; oB1[i] = 0.f; }

    float inv0 = 0.f, inv1 = 0.f, inv2 = 0.f, inv3 = 0.f;
    float* outp = out + (size_t)b * DYN * PLANE + h * WW + w;

    for (int p = 0; p < 32; p++) {
        asm volatile("cp.async.wait_group 1;\n" ::: "memory");
        __syncthreads();
        if (p + 2 < 32) {
            int ch = (p + 2 < 16) ? (DYN + 2 * (p + 2)) : (2 * (p + 2) - 32);
            pf(sbuf[(p + 2) % 3], base + (size_t)ch * PLANE);
        } else {
            asm volatile("cp.async.commit_group;\n");   // keep group counts uniform
        }

        const float* tb0 = &tiles[p % 3][0];
        const float* tb1 = tb0 + TELEMS;

        if (p < 16) {
            PHASE1(tb0)
            PHASE1(tb1)
        } else {
            if (p == 16) {
                // ---- Softmax over 25 taps (per pixel), once ----
                float m0 = -3.0e38f, m1 = m0, m2 = m0, m3 = m0;
#pragma unroll
                for (int q = 0; q < 5; q++) {
#pragma unroll
                    for (int jj = 0; jj < 3; jj++) {
                        float kk = kw[q * 5 + 2 * jj];
                        float s0, s1, s2, s3;
                        unpk(sA[q*3+jj], s0, s1); unpk(sB[q*3+jj], s2, s3);
                        s0 *= kk; s1 *= kk; s2 *= kk; s3 *= kk;
                        sA[q*3+jj] = pk(s0, s1); sB[q*3+jj] = pk(s2, s3);
                        m0 = fmaxf(m0, s0); m1 = fmaxf(m1, s1);
                        m2 = fmaxf(m2, s2); m3 = fmaxf(m3, s3);
                    }
#pragma unroll
                    for (int jj = 0; jj < 2; jj++) {
                        float kk = kw[q * 5 + 2 * jj + 1];
                        oA0[q*2+jj] *= kk; oA1[q*2+jj] *= kk;
                        oB0[q*2+jj] *= kk; oB1[q*2+jj] *= kk;
                        m0 = fmaxf(m0, oA0[q*2+jj]); m1 = fmaxf(m1, oA1[q*2+jj]);
                        m2 = fmaxf(m2, oB0[q*2+jj]); m3 = fmaxf(m3, oB1[q*2+jj]);
                    }
                }
                float t0 = 0.f, t1 = 0.f, t2 = 0.f, t3 = 0.f;
#pragma unroll
                for (int q = 0; q < 15; q++) {
                    float s0, s1, s2, s3;
                    unpk(sA[q], s0, s1); unpk(sB[q], s2, s3);
                    s0 = __expf(s0 - m0); s1 = __expf(s1 - m1);
                    s2 = __expf(s2 - m2); s3 = __expf(s3 - m3);
                    t0 += s0; t1 += s1; t2 += s2; t3 += s3;
                    sA[q] = pk(s0, s1); sB[q] = pk(s2, s3);
                }
#pragma unroll
                for (int q = 0; q < 10; q++) {
                    float e0 = __expf(oA0[q] - m0), e1 = __expf(oA1[q] - m1);
                    float e2 = __expf(oB0[q] - m2), e3 = __expf(oB1[q] - m3);
                    oA0[q] = e0; oA1[q] = e1; oB0[q] = e2; oB1[q] = e3;
                    t0 += e0; t1 += e1; t2 += e2; t3 += e3;
                }
                inv0 = __fdividef(1.f, t0); inv1 = __fdividef(1.f, t1);
                inv2 = __fdividef(1.f, t2); inv3 = __fdividef(1.f, t3);
            }
            PHASE2(tb0, 2 * (p - 16))
            PHASE2(tb1, 2 * (p - 16) + 1)
        }
    }
}

extern "C" void kernel_launch(void* const* d_in, const int* in_sizes, int n_in,
                              void* d_out, int out_size) {
    const float* x = (const float*)d_in[0];
    const float* k = (const float*)d_in[1];
    float* o       = (float*)d_out;
    dim3 block(NTHR, 1, 1);
    dim3 grid(WW / TILE_W, HH / TILE_H, 4);   // 8 x 32 x 4 = 1024 blocks
    local_attn_kernel<<<grid, block>>>(x, k, o);
}

// round 11
// speedup vs baseline: 1.6018x; 1.1095x over previous
#include <cuda_runtime.h>

namespace {
constexpr int HH     = 256;
constexpr int WW     = 256;
constexpr int NC     = 64;
constexpr int DYN    = 32;
constexpr int TILE_W = 32;
constexpr int TILE_H = 8;
constexpr int SH     = 12;           // TILE_H + 4 halo rows
constexpr int SW     = 40;           // 160B rows (16B aligned)
constexpr int NTHR   = 64;
constexpr int PLANE  = HH * WW;
constexpr int ROW_CHUNKS = 10;       // 40 floats = 10 x 16B
constexpr int CHUNKS = SH * ROW_CHUNKS;   // 120
constexpr int TELEMS = SH * SW;      // 480 floats per channel tile
constexpr int TBYTES = TELEMS * 4;   // 1920 bytes
}

__device__ __forceinline__ ulonglong2 ld128s(const float* p) {
    return *reinterpret_cast<const ulonglong2*>(p);
}
__device__ __forceinline__ void unpk(unsigned long long v, float& a, float& b) {
    asm("mov.b64 {%0, %1}, %2;" : "=f"(a), "=f"(b) : "l"(v));
}
__device__ __forceinline__ unsigned long long pk(float a, float b) {
    unsigned long long v;
    asm("mov.b64 %0, {%1, %2};" : "=l"(v) : "f"(a), "f"(b));
    return v;
}
__device__ __forceinline__ unsigned long long ffma2(unsigned long long a,
                                                    unsigned long long b,
                                                    unsigned long long c) {
    unsigned long long d;
    asm("fma.rn.f32x2 %0, %1, %2, %3;" : "=l"(d) : "l"(a), "l"(b), "l"(c));
    return d;
}
__device__ __forceinline__ unsigned smem_u32(const void* p) {
    unsigned r;
    asm("{ .reg .u64 t; cvta.to.shared.u64 t, %1; cvt.u32.u64 %0, t; }"
        : "=r"(r) : "l"(p));
    return r;
}
__device__ __forceinline__ void cp16(unsigned dst, const float* src) {
    asm volatile("cp.async.cg.shared.global [%0], [%1], 16;\n"
                 :: "r"(dst), "l"(src));
}

// Pixel remap: thread owns pixels at tile cols 4tx+2..4tx+5 (global
// 32bx-2+4tx..+3). Its 5-tap window = tile cols 4tx..4tx+7 => TWO aligned
// LDS.128 (g0, g1). Pairs: P0=g0.x P1=g0.y P2=g1.x P3=g1.y.
#define SCORE_BODY(P0, P1, P2, P3, r)                                         \
    {                                                                         \
        float p0x, p0y, p1x, p1y, p2x, p2y, p3x, p3y;                         \
        unpk(P0, p0x, p0y); unpk(P1, p1x, p1y);                               \
        unpk(P2, p2x, p2y); unpk(P3, p3x, p3y);                               \
        (void)p0x; (void)p3y;                                                 \
        sA[(r)*3+0] = ffma2(P0, cA, sA[(r)*3+0]);                             \
        sA[(r)*3+1] = ffma2(P1, cA, sA[(r)*3+1]);                             \
        sA[(r)*3+2] = ffma2(P2, cA, sA[(r)*3+2]);                             \
        sB[(r)*3+0] = ffma2(P1, cB, sB[(r)*3+0]);                             \
        sB[(r)*3+1] = ffma2(P2, cB, sB[(r)*3+1]);                             \
        sB[(r)*3+2] = ffma2(P3, cB, sB[(r)*3+2]);                             \
        oA0[(r)*2+0] = fmaf(p0y, cA0, oA0[(r)*2+0]);                          \
        oA1[(r)*2+0] = fmaf(p1x, cA1, oA1[(r)*2+0]);                          \
        oA0[(r)*2+1] = fmaf(p1y, cA0, oA0[(r)*2+1]);                          \
        oA1[(r)*2+1] = fmaf(p2x, cA1, oA1[(r)*2+1]);                          \
        oB0[(r)*2+0] = fmaf(p1y, cB0, oB0[(r)*2+0]);                          \
        oB1[(r)*2+0] = fmaf(p2x, cB1, oB1[(r)*2+0]);                          \
        oB0[(r)*2+1] = fmaf(p2y, cB0, oB0[(r)*2+1]);                          \
        oB1[(r)*2+1] = fmaf(p3x, cB1, oB1[(r)*2+1]);                          \
    }

#define SCORE_ROW(r)                                                          \
    {                                                                         \
        const float* rowp = tbase + (ty + (r)) * SW + 4 * tx;                 \
        ulonglong2 g0 = ld128s(rowp);                                         \
        ulonglong2 g1 = ld128s(rowp + 4);                                     \
        SCORE_BODY(g0.x, g0.y, g1.x, g1.y, r)                                 \
    }

// Full phase-1 pass (center row first; center pair = g0.y / g1.x, free).
#define PHASE1(TB)                                                            \
    {                                                                         \
        const float* tbase = (TB);                                            \
        unsigned long long cA, cB;                                            \
        float cA0, cA1, cB0, cB1;                                             \
        {                                                                     \
            const float* rowp = tbase + (ty + 2) * SW + 4 * tx;               \
            ulonglong2 g0 = ld128s(rowp);                                     \
            ulonglong2 g1 = ld128s(rowp + 4);                                 \
            cA = g0.y; cB = g1.x;                                             \
            unpk(cA, cA0, cA1); unpk(cB, cB0, cB1);                           \
            SCORE_BODY(g0.x, g0.y, g1.x, g1.y, 2)                             \
        }                                                                     \
        SCORE_ROW(0)                                                          \
        SCORE_ROW(1)                                                          \
        SCORE_ROW(3)                                                          \
        SCORE_ROW(4)                                                          \
    }

// Full phase-2 pass, storing output channel CH with edge predication.
#define PHASE2(TB, CH)                                                        \
    {                                                                         \
        const float* tbase = (TB);                                            \
        unsigned long long accA = 0ull, accB = 0ull;                          \
        float a0 = 0.f, a1 = 0.f, a2 = 0.f, a3 = 0.f;                         \
        _Pragma("unroll")                                                     \
        for (int r = 0; r < 5; r++) {                                         \
            const float* rowp = tbase + (ty + r) * SW + 4 * tx;               \
            ulonglong2 g0 = ld128s(rowp);                                     \
            ulonglong2 g1 = ld128s(rowp + 4);                                 \
            unsigned long long P0 = g0.x, P1 = g0.y, P2 = g1.x, P3 = g1.y;    \
            float p0x, p0y, p1x, p1y, p2x, p2y, p3x, p3y;                     \
            unpk(P0, p0x, p0y); unpk(P1, p1x, p1y);                           \
            unpk(P2, p2x, p2y); unpk(P3, p3x, p3y);                           \
            (void)p0x; (void)p3y;                                             \
            accA = ffma2(P0, sA[r*3+0], accA);                                \
            accA = ffma2(P1, sA[r*3+1], accA);                                \
            accA = ffma2(P2, sA[r*3+2], accA);                                \
            accB = ffma2(P1, sB[r*3+0], accB);                                \
            accB = ffma2(P2, sB[r*3+1], accB);                                \
            accB = ffma2(P3, sB[r*3+2], accB);                                \
            a0 = fmaf(p0y, oA0[r*2+0], a0);                                   \
            a1 = fmaf(p1x, oA1[r*2+0], a1);                                   \
            a0 = fmaf(p1y, oA0[r*2+1], a0);                                   \
            a1 = fmaf(p2x, oA1[r*2+1], a1);                                   \
            a2 = fmaf(p1y, oB0[r*2+0], a2);                                   \
            a3 = fmaf(p2x, oB1[r*2+0], a3);                                   \
            a2 = fmaf(p2y, oB0[r*2+1], a2);                                   \
            a3 = fmaf(p3x, oB1[r*2+1], a3);                                   \
        }                                                                     \
        float A0, A1, Bv0, Bv1;                                               \
        unpk(accA, A0, A1); unpk(accB, Bv0, Bv1);                             \
        float r0 = (A0 + a0) * inv0;                                          \
        float r1 = (A1 + a1) * inv1;                                          \
        float r2 = (Bv0 + a2) * inv2;                                         \
        float r3 = (Bv1 + a3) * inv3;                                         \
        float* op = outp + (size_t)(CH) * PLANE;                              \
        if (allv) {                                                           \
            *reinterpret_cast<float2*>(op)     = make_float2(r0, r1);         \
            *reinterpret_cast<float2*>(op + 2) = make_float2(r2, r3);         \
        } else {                                                              \
            if ((unsigned)(pbase + 0) < (unsigned)WW) op[0] = r0;             \
            if ((unsigned)(pbase + 1) < (unsigned)WW) op[1] = r1;             \
            if ((unsigned)(pbase + 2) < (unsigned)WW) op[2] = r2;             \
            if ((unsigned)(pbase + 3) < (unsigned)WW) op[3] = r3;             \
        }                                                                     \
    }

extern "C" __global__ void __launch_bounds__(NTHR, 7)
local_attn_kernel(const float* __restrict__ x, const float* __restrict__ kern,
                  float* __restrict__ out) {
    const int tid = threadIdx.x;
    const int tx  = tid & 7;
    const int ty  = tid >> 3;           // 0..7
    const int b   = blockIdx.z;
    const int h0  = blockIdx.y * TILE_H;
    const int w0  = blockIdx.x * TILE_W;   // bx 0..8; tile col t <-> global w0-4+t
    const int h   = h0 + ty;
    const int pbase = w0 - 2 + 4 * tx;     // leftmost owned pixel (may be OOB)
    const bool allv = (pbase >= 0) && (pbase + 3 < WW);

    __shared__ __align__(16) float tiles[3][2 * TELEMS];   // slot = 2 channels
    __shared__ float kw[32];
    if (tid < 25) kw[tid] = kern[tid] * 0.2f;   // kernel[k] / KSIZE

    // zero-fill all buffers once (border chunks stay zero forever)
    {
        float4 z = make_float4(0.f, 0.f, 0.f, 0.f);
        float4* tz = reinterpret_cast<float4*>(&tiles[0][0]);
        const int n4 = 3 * 2 * TELEMS / 4;   // 720
#pragma unroll
        for (int i = 0; i < 12; i++) {
            int idx = tid + i * NTHR;
            if (idx < n4) tz[idx] = z;
        }
    }
    __syncthreads();

    // ---- Precompute prefetch chunk descriptors (channel-invariant) ----
    bool vA, vB;
    unsigned soA, soB;
    int goA, goB;
    {
        int idx = tid;                       // chunk 0: always < 120
        int r = idx / ROW_CHUNKS, c = idx - r * ROW_CHUNKS;
        int gh = h0 + r - 2, gw = w0 - 4 + 4 * c;
        vA  = ((unsigned)gh < (unsigned)HH) && (gw >= 0) && (gw + 4 <= WW);
        soA = (unsigned)(r * SW + 4 * c) * 4u;
        goA = gh * WW + gw;

        idx = tid + NTHR;                    // chunk 1: valid only if < 120
        r = idx / ROW_CHUNKS; c = idx - r * ROW_CHUNKS;
        gh = h0 + r - 2; gw = w0 - 4 + 4 * c;
        vB  = (idx < CHUNKS) && ((unsigned)gh < (unsigned)HH) &&
              (gw >= 0) && (gw + 4 <= WW);
        soB = (unsigned)(r * SW + 4 * c) * 4u;
        goB = gh * WW + gw;
    }

    const float* base = x + (size_t)b * NC * PLANE;
    unsigned sbuf[3] = { smem_u32(&tiles[0][0]), smem_u32(&tiles[1][0]),
                         smem_u32(&tiles[2][0]) };

    auto pf = [&](unsigned sb, const float* planeA) {
        if (vA) { cp16(sb + soA, planeA + goA);
                  cp16(sb + TBYTES + soA, planeA + PLANE + goA); }
        if (vB) { cp16(sb + soB, planeA + goB);
                  cp16(sb + TBYTES + soB, planeA + PLANE + goB); }
        asm volatile("cp.async.commit_group;\n");
    };

    pf(sbuf[0], base + (size_t)(DYN + 0) * PLANE);   // ch 32,33
    pf(sbuf[1], base + (size_t)(DYN + 2) * PLANE);   // ch 34,35

    // accumulators: even-j taps packed f32x2, odd-j taps scalar
    unsigned long long sA[15], sB[15];
    float oA0[10], oA1[10], oB0[10], oB1[10];
#pragma unroll
    for (int i = 0; i < 15; i++) { sA[i] = 0ull; sB[i] = 0ull; }
#pragma unroll
    for (int i = 0; i < 10; i++) { oA0[i] = 0.f; oA1[i] = 0.f; oB0[i] = 0.f; oB1[i] = 0.f; }

    float inv0 = 0.f, inv1 = 0.f, inv2 = 0.f, inv3 = 0.f;
    float* outp = out + (size_t)b * DYN * PLANE + h * WW + pbase;

    for (int p = 0; p < 32; p++) {
        asm volatile("cp.async.wait_group 1;\n" ::: "memory");
        __syncthreads();
        if (p + 2 < 32) {
            int ch = (p + 2 < 16) ? (DYN + 2 * (p + 2)) : (2 * (p + 2) - 32);
            pf(sbuf[(p + 2) % 3], base + (size_t)ch * PLANE);
        } else {
            asm volatile("cp.async.commit_group;\n");   // keep group counts uniform
        }

        const float* tb0 = &tiles[p % 3][0];
        const float* tb1 = tb0 + TELEMS;

        if (p < 16) {
            PHASE1(tb0)
            PHASE1(tb1)
        } else {
            if (p == 16) {
                // ---- Softmax over 25 taps (per pixel), once ----
                float m0 = -3.0e38f, m1 = m0, m2 = m0, m3 = m0;
#pragma unroll
                for (int q = 0; q < 5; q++) {
#pragma unroll
                    for (int jj = 0; jj < 3; jj++) {
                        float kk = kw[q * 5 + 2 * jj];
                        float s0, s1, s2, s3;
                        unpk(sA[q*3+jj], s0, s1); unpk(sB[q*3+jj], s2, s3);
                        s0 *= kk; s1 *= kk; s2 *= kk; s3 *= kk;
                        sA[q*3+jj] = pk(s0, s1); sB[q*3+jj] = pk(s2, s3);
                        m0 = fmaxf(m0, s0); m1 = fmaxf(m1, s1);
                        m2 = fmaxf(m2, s2); m3 = fmaxf(m3, s3);
                    }
#pragma unroll
                    for (int jj = 0; jj < 2; jj++) {
                        float kk = kw[q * 5 + 2 * jj + 1];
                        oA0[q*2+jj] *= kk; oA1[q*2+jj] *= kk;
                        oB0[q*2+jj] *= kk; oB1[q*2+jj] *= kk;
                        m0 = fmaxf(m0, oA0[q*2+jj]); m1 = fmaxf(m1, oA1[q*2+jj]);
                        m2 = fmaxf(m2, oB0[q*2+jj]); m3 = fmaxf(m3, oB1[q*2+jj]);
                    }
                }
                float t0 = 0.f, t1 = 0.f, t2 = 0.f, t3 = 0.f;
#pragma unroll
                for (int q = 0; q < 15; q++) {
                    float s0, s1, s2, s3;
                    unpk(sA[q], s0, s1); unpk(sB[q], s2, s3);
                    s0 = __expf(s0 - m0); s1 = __expf(s1 - m1);
                    s2 = __expf(s2 - m2); s3 = __expf(s3 - m3);
                    t0 += s0; t1 += s1; t2 += s2; t3 += s3;
                    sA[q] = pk(s0, s1); sB[q] = pk(s2, s3);
                }
#pragma unroll
                for (int q = 0; q < 10; q++) {
                    float e0 = __expf(oA0[q] - m0), e1 = __expf(oA1[q] - m1);
                    float e2 = __expf(oB0[q] - m2), e3 = __expf(oB1[q] - m3);
                    oA0[q] = e0; oA1[q] = e1; oB0[q] = e2; oB1[q] = e3;
                    t0 += e0; t1 += e1; t2 += e2; t3 += e3;
                }
                inv0 = __fdividef(1.f, t0); inv1 = __fdividef(1.f, t1);
                inv2 = __fdividef(1.f, t2); inv3 = __fdividef(1.f, t3);
            }
            PHASE2(tb0, 2 * (p - 16))
            PHASE2(tb1, 2 * (p - 16) + 1)
        }
    }
}

extern "C" void kernel_launch(void* const* d_in, const int* in_sizes, int n_in,
                              void* d_out, int out_size) {
    const float* x = (const float*)d_in[0];
    const float* k = (const float*)d_in[1];
    float* o       = (float*)d_out;
    dim3 block(NTHR, 1, 1);
    // 9 x-blocks: block bx covers pixels [32bx-2, 32bx+30); edge columns
    // partially predicated. 9 x 32 x 4 = 1152 blocks.
    dim3 grid(WW / TILE_W + 1, HH / TILE_H, 4);
    local_attn_kernel<<<grid, block>>>(x, k, o);
}